// round 1
// baseline (speedup 1.0000x reference)
#include <cuda_runtime.h>
#include <math.h>

#define BB 8
#define TT 256
#define KK 20
#define HH 768
#define VV 30522
#define TM1 255           // T-1
#define MR (TM1*BB)       // 2040 rows (t-major: r = t*BB + b)
#define G4 (4*HH)         // 3072
#define NEG_INF (-1e30f)

// ---------------- scratch (static device memory; no runtime allocs) ---------
static __device__ float g_trans[KK*KK];
static __device__ float g_emis[BB*TT*KK];          // [b][t][k]
static __device__ float g_alphas[TT*BB*KK];        // [t][b][k]
static __device__ float g_relaxed[TT*BB*KK];       // [t][b][k]
static __device__ int   g_z[TT*BB];                // [t][b]
static __device__ float g_enttok[BB*TT];           // [b][t]
static __device__ float g_dec[(size_t)MR*HH];      // [r][h]
static __device__ float g_wih_r[(size_t)G4*HH];    // [j'][k], j' = m*4+g
static __device__ float g_whh_r[(size_t)HH*G4];    // [k][m*4+g]
static __device__ float g_b4[G4];                  // [m*4+g]
static __device__ float g_xw[(size_t)MR*G4];       // [r][m*4+g]
static __device__ float g_h[(size_t)MR*HH];        // [r][h]
static __device__ float g_c[BB*HH];
static __device__ float g_logits[(size_t)MR*VV];   // 249 MB
static __device__ float g_lse[MR];
static __device__ float g_tgtl[MR];

__device__ __forceinline__ float sigmoidf(float x){ return 1.f/(1.f+expf(-x)); }

// ---------------- transition = S @ S^T --------------------------------------
__global__ void k_trans(const float* __restrict__ S)
{
    int i = blockIdx.x, j = blockIdx.y;
    float s = 0.f;
    for (int k = threadIdx.x; k < HH; k += 128) s += S[i*HH+k]*S[j*HH+k];
    __shared__ float red[128];
    red[threadIdx.x] = s; __syncthreads();
    for (int o = 64; o > 0; o >>= 1) {
        if (threadIdx.x < o) red[threadIdx.x] += red[threadIdx.x+o];
        __syncthreads();
    }
    if (threadIdx.x == 0) g_trans[i*KK+j] = red[0];
}

// ---------------- emission[b][t][k] = x_emb[b][t] . S[k] --------------------
__global__ void k_emis(const float* __restrict__ xemb, const float* __restrict__ S)
{
    int bt = blockIdx.x;                         // b*TT + t
    const float* xr = xemb + (size_t)bt*HH;
    int w = threadIdx.x >> 5, lane = threadIdx.x & 31;
    for (int k = w; k < KK; k += 8) {
        const float* sr = S + (size_t)k*HH;
        float s = 0.f;
        for (int i = lane; i < HH; i += 32) s += xr[i]*sr[i];
        for (int o = 16; o > 0; o >>= 1) s += __shfl_down_sync(0xffffffffu, s, o);
        if (lane == 0) g_emis[(size_t)bt*KK + k] = s;
    }
}

// ---------------- per-token entropy of softmax(emission) --------------------
__global__ void k_ent()
{
    int bt = blockIdx.x*256 + threadIdx.x;       // < BB*TT
    const float* e = g_emis + (size_t)bt*KK;
    float m = NEG_INF;
    for (int k = 0; k < KK; k++) m = fmaxf(m, e[k]);
    float se = 0.f;
    for (int k = 0; k < KK; k++) se += expf(e[k]-m);
    float lse = m + logf(se);
    float ent = 0.f;
    for (int k = 0; k < KK; k++) { float lp = e[k]-lse; ent -= expf(lp)*lp; }
    g_enttok[bt] = ent;
}

// ---------------- CRF forward recursion (sequential in t) -------------------
__global__ void k_fwd()
{
    __shared__ float sa[BB*KK];
    __shared__ float tr[KK*KK];
    int tid = threadIdx.x;
    for (int i = tid; i < KK*KK; i += blockDim.x) tr[i] = g_trans[i];
    if (tid < BB*KK) {
        int b = tid / KK, j = tid % KK;
        float a0 = g_emis[((size_t)b*TT + 0)*KK + j];
        sa[tid] = a0;
        g_alphas[tid] = a0;                      // t=0 slot
    }
    __syncthreads();
    for (int t = 1; t < TT; t++) {
        float a = 0.f;
        if (tid < BB*KK) {
            int b = tid / KK, j = tid % KK;
            float m = NEG_INF;
            #pragma unroll
            for (int k = 0; k < KK; k++) m = fmaxf(m, sa[b*KK+k] + tr[k*KK+j]);
            float se = 0.f;
            #pragma unroll
            for (int k = 0; k < KK; k++) se += expf(sa[b*KK+k] + tr[k*KK+j] - m);
            a = m + logf(se) + g_emis[((size_t)b*TT + t)*KK + j];
        }
        __syncthreads();
        if (tid < BB*KK) { sa[tid] = a; g_alphas[(size_t)t*BB*KK + tid] = a; }
        __syncthreads();
    }
}

// ---------------- relaxed backward sampling (warp b, lane k) ----------------
// argmax & softmax of (log_softmax(logits)+g) are shift-invariant -> skip lse.
__global__ void k_bwd(const float* __restrict__ gum)   // gum [t][b][k]
{
    int b = threadIdx.x >> 5, lane = threadIdx.x & 31;
    __shared__ float tr[KK*KK];
    for (int i = threadIdx.x; i < KK*KK; i += blockDim.x) tr[i] = g_trans[i];
    __syncthreads();
    int zn = 0;
    for (int t = TT-1; t >= 0; t--) {
        float y = NEG_INF;
        if (lane < KK) {
            float al = g_alphas[((size_t)t*BB + b)*KK + lane];
            float tv = (t == TT-1) ? 0.f : tr[lane*KK + zn];
            y = al + tv + gum[((size_t)t*BB + b)*KK + lane];
        }
        // argmax with lowest-index tiebreak (matches jnp.argmax)
        float bv = y; int bi = lane;
        for (int o = 16; o > 0; o >>= 1) {
            float ov = __shfl_down_sync(0xffffffffu, bv, o);
            int   oi = __shfl_down_sync(0xffffffffu, bi, o);
            if (ov > bv || (ov == bv && oi < bi)) { bv = ov; bi = oi; }
        }
        bv = __shfl_sync(0xffffffffu, bv, 0);
        bi = __shfl_sync(0xffffffffu, bi, 0);
        float e = (lane < KK) ? expf(y - bv) : 0.f;   // TAU = 1
        float se = e;
        for (int o = 16; o > 0; o >>= 1) se += __shfl_down_sync(0xffffffffu, se, o);
        se = __shfl_sync(0xffffffffu, se, 0);
        if (lane < KK) g_relaxed[((size_t)t*BB + b)*KK + lane] = e / se;
        if (lane == 0) g_z[t*BB + b] = bi;
        zn = bi;
    }
}

// ---------------- dec_in[r][h] = relaxed[t,b,:] @ S + emb[x[b][t]] ----------
__global__ void k_dec(const float* __restrict__ S, const float* __restrict__ emb,
                      const int* __restrict__ x)
{
    int r = blockIdx.x;                           // r = t*BB + b, t < TM1
    int t = r / BB, b = r % BB;
    __shared__ float rl[KK];
    if (threadIdx.x < KK) rl[threadIdx.x] = g_relaxed[((size_t)t*BB + b)*KK + threadIdx.x];
    __syncthreads();
    const float* er = emb + (size_t)x[b*TT + t]*HH;
    for (int h = threadIdx.x; h < HH; h += 256) {
        float s = er[h];
        #pragma unroll
        for (int k = 0; k < KK; k++) s += rl[k]*S[(size_t)k*HH + h];
        g_dec[(size_t)r*HH + h] = s;
    }
}

// ---------------- weight repacking (gate-interleaved) -----------------------
__global__ void k_packwih(const float* __restrict__ W)
{
    size_t i = (size_t)blockIdx.x*256 + threadIdx.x;
    if (i >= (size_t)G4*HH) return;
    int jp = (int)(i / HH), k = (int)(i % HH);
    int g = jp & 3, m = jp >> 2;
    g_wih_r[i] = W[(size_t)(g*HH + m)*HH + k];
}
__global__ void k_packwhh(const float* __restrict__ W)
{
    size_t i = (size_t)blockIdx.x*256 + threadIdx.x;
    if (i >= (size_t)HH*G4) return;
    int k = (int)(i / G4), j = (int)(i % G4);
    int m = j >> 2, g = j & 3;
    g_whh_r[i] = W[(size_t)(g*HH + m)*HH + k];
}
__global__ void k_packb(const float* __restrict__ bl)
{
    int j = blockIdx.x*256 + threadIdx.x;
    if (j < G4) g_b4[j] = bl[(j & 3)*HH + (j >> 2)];
}

// ---------------- fp32 NT GEMM: C[M,N] = A[M,768] * Bm[N,768]^T + bias ------
__global__ void __launch_bounds__(256)
k_sgemm(const float* __restrict__ A, const float* __restrict__ Bm,
        const float* __restrict__ bias, float* __restrict__ C, int M, int N)
{
    const int K = HH;
    __shared__ __align__(16) float As[16][64];
    __shared__ __align__(16) float Bs[16][64];
    int bn0 = blockIdx.x*64, bm0 = blockIdx.y*64;
    int tid = threadIdx.x;
    int tx = tid & 15, ty = tid >> 4;
    int lr = tid >> 2, lk = (tid & 3)*4;
    float acc[16];
    #pragma unroll
    for (int i = 0; i < 16; i++) acc[i] = 0.f;
    const float* Ap = A + (size_t)(bm0+lr)*K + lk;
    const float* Bp = Bm + (size_t)(bn0+lr)*K + lk;
    bool aval = (bm0+lr) < M;
    bool bval = (bn0+lr) < N;
    for (int k0 = 0; k0 < K; k0 += 16) {
        float4 av = aval ? *(const float4*)(Ap + k0) : make_float4(0,0,0,0);
        float4 bv = bval ? *(const float4*)(Bp + k0) : make_float4(0,0,0,0);
        As[lk+0][lr]=av.x; As[lk+1][lr]=av.y; As[lk+2][lr]=av.z; As[lk+3][lr]=av.w;
        Bs[lk+0][lr]=bv.x; Bs[lk+1][lr]=bv.y; Bs[lk+2][lr]=bv.z; Bs[lk+3][lr]=bv.w;
        __syncthreads();
        #pragma unroll
        for (int kk = 0; kk < 16; kk++) {
            float4 a = *(const float4*)&As[kk][ty*4];
            float4 b = *(const float4*)&Bs[kk][tx*4];
            acc[0]  += a.x*b.x; acc[1]  += a.x*b.y; acc[2]  += a.x*b.z; acc[3]  += a.x*b.w;
            acc[4]  += a.y*b.x; acc[5]  += a.y*b.y; acc[6]  += a.y*b.z; acc[7]  += a.y*b.w;
            acc[8]  += a.z*b.x; acc[9]  += a.z*b.y; acc[10] += a.z*b.z; acc[11] += a.z*b.w;
            acc[12] += a.w*b.x; acc[13] += a.w*b.y; acc[14] += a.w*b.z; acc[15] += a.w*b.w;
        }
        __syncthreads();
    }
    #pragma unroll
    for (int i = 0; i < 4; i++) {
        int r = bm0 + ty*4 + i;
        if (r >= M) continue;
        #pragma unroll
        for (int j = 0; j < 4; j++) {
            int c = bn0 + tx*4 + j;
            if (c < N) C[(size_t)r*N + c] = acc[i*4+j] + (bias ? bias[c] : 0.f);
        }
    }
}

// ---------------- one LSTM timestep -----------------------------------------
__global__ void k_lstm(int t)
{
    int b = blockIdx.y;
    int m = blockIdx.x*256 + threadIdx.x;        // hidden unit
    __shared__ float hs[HH];
    if (t > 0) {
        const float* hp = g_h + ((size_t)(t-1)*BB + b)*HH;
        for (int i = threadIdx.x; i < HH; i += 256) hs[i] = hp[i];
    }
    __syncthreads();
    float4 acc = *(const float4*)(g_xw + ((size_t)t*BB + b)*G4 + m*4);  // bias already in
    if (t > 0) {
        const float4* W = (const float4*)g_whh_r;
        #pragma unroll 8
        for (int k = 0; k < HH; k++) {
            float hk = hs[k];
            float4 w = W[(size_t)k*HH + m];
            acc.x += hk*w.x; acc.y += hk*w.y; acc.z += hk*w.z; acc.w += hk*w.w;
        }
    }
    float c_old = (t > 0) ? g_c[b*HH + m] : 0.f;
    float ig = sigmoidf(acc.x), fg = sigmoidf(acc.y);
    float gg = tanhf(acc.z),    og = sigmoidf(acc.w);
    float c  = fg*c_old + ig*gg;
    float h  = og*tanhf(c);
    g_c[b*HH + m] = c;
    g_h[((size_t)t*BB + b)*HH + m] = h;
}

// ---------------- per-row logsumexp over V + target logit gather ------------
__global__ void k_lse(const int* __restrict__ x)
{
    int r = blockIdx.x;
    int t = r / BB, b = r % BB;
    const float* L = g_logits + (size_t)r*VV;
    int tid = threadIdx.x;
    float m = NEG_INF, s = 0.f;
    for (int v = tid; v < VV; v += 256) {
        float val = L[v];
        if (val > m) { s = s*expf(m - val) + 1.f; m = val; }
        else          s += expf(val - m);
    }
    __shared__ float sm[256], ss[256];
    sm[tid] = m; ss[tid] = s; __syncthreads();
    for (int o = 128; o > 0; o >>= 1) {
        if (tid < o) {
            float m2 = sm[tid+o], s2 = ss[tid+o];
            float mm = fmaxf(sm[tid], m2);
            ss[tid] = ss[tid]*expf(sm[tid]-mm) + s2*expf(m2-mm);
            sm[tid] = mm;
        }
        __syncthreads();
    }
    if (tid == 0) {
        g_lse[r]  = sm[0] + logf(ss[0]);
        g_tgtl[r] = L[x[b*TT + t + 1]];
    }
}

// ---------------- final loss + output ---------------------------------------
__global__ void k_final(const int* __restrict__ am, float* __restrict__ out, int out_size)
{
    int tid = threadIdx.x;
    float s_ent = 0.f, s_m = 0.f, s_lp = 0.f, s_tm = 0.f;
    for (int i = tid; i < BB*TT; i += 256) {
        float mk = (float)am[i];
        s_ent += g_enttok[i]*mk;
        s_m   += mk;
    }
    for (int r = tid; r < MR; r += 256) {
        int t = r / BB, b = r % BB;
        float mk = (float)am[b*TT + t + 1];
        s_lp += (g_tgtl[r] - g_lse[r])*mk;
        s_tm += mk;
    }
    __shared__ float r0[256], r1[256], r2[256], r3[256];
    r0[tid]=s_ent; r1[tid]=s_m; r2[tid]=s_lp; r3[tid]=s_tm;
    __syncthreads();
    for (int o = 128; o > 0; o >>= 1) {
        if (tid < o) { r0[tid]+=r0[tid+o]; r1[tid]+=r1[tid+o];
                       r2[tid]+=r2[tid+o]; r3[tid]+=r3[tid+o]; }
        __syncthreads();
    }
    if (tid == 0) {
        float loss = -((r2[0]/r3[0]) + 1.0f*(r0[0]/r1[0]));   // Z_BETA = 1
        if (out_size != BB*TT) out[0] = loss;                 // unless z-only layout
    }
    __syncthreads();
    int off = (out_size == BB*TT) ? 0 : 1;
    if (out_size >= BB*TT + off) {
        for (int i = tid; i < BB*TT; i += 256) {
            int b = i / TT, t = i % TT;
            out[off + i] = (float)g_z[t*BB + b];              // z_sample[b][t]
        }
    }
}

// ---------------- host ------------------------------------------------------
extern "C" void kernel_launch(void* const* d_in, const int* in_sizes, int n_in,
                              void* d_out, int out_size)
{
    (void)in_sizes; (void)n_in;
    const float* x_emb = (const float*)d_in[0];
    const float* S     = (const float*)d_in[1];
    const float* emb   = (const float*)d_in[2];
    const float* Wih   = (const float*)d_in[3];
    const float* Whh   = (const float*)d_in[4];
    const float* bl    = (const float*)d_in[5];
    const float* Wout  = (const float*)d_in[6];
    const float* bout  = (const float*)d_in[7];
    const float* gum   = (const float*)d_in[8];
    const int*   x     = (const int*)d_in[9];
    const int*   am    = (const int*)d_in[10];

    float *p_dec, *p_wihr, *p_b4, *p_xw, *p_h, *p_logits;
    cudaGetSymbolAddress((void**)&p_dec,    g_dec);
    cudaGetSymbolAddress((void**)&p_wihr,   g_wih_r);
    cudaGetSymbolAddress((void**)&p_b4,     g_b4);
    cudaGetSymbolAddress((void**)&p_xw,     g_xw);
    cudaGetSymbolAddress((void**)&p_h,      g_h);
    cudaGetSymbolAddress((void**)&p_logits, g_logits);

    dim3 gt(KK, KK);
    k_trans<<<gt, 128>>>(S);
    k_emis<<<BB*TT, 256>>>(x_emb, S);
    k_ent<<<(BB*TT)/256, 256>>>();
    k_fwd<<<1, 256>>>();
    k_bwd<<<1, BB*32>>>(gum);
    k_dec<<<MR, 256>>>(S, emb, x);
    k_packwih<<<(int)(((size_t)G4*HH + 255)/256), 256>>>(Wih);
    k_packwhh<<<(int)(((size_t)HH*G4 + 255)/256), 256>>>(Whh);
    k_packb<<<(G4 + 255)/256, 256>>>(bl);

    // xW = dec_in @ W_ih^T (gate-interleaved) + b
    k_sgemm<<<dim3(G4/64, (MR + 63)/64), 256>>>(p_dec, p_wihr, p_b4, p_xw, MR, G4);

    // sequential LSTM
    for (int t = 0; t < TM1; t++)
        k_lstm<<<dim3(HH/256, BB), 256>>>(t);

    // logits = hs @ W_out^T + b_out
    k_sgemm<<<dim3((VV + 63)/64, (MR + 63)/64), 256>>>(p_h, Wout, bout, p_logits, MR, VV);

    k_lse<<<MR, 256>>>(x);
    k_final<<<1, 256>>>(am, (float*)d_out, out_size);
}

// round 3
// speedup vs baseline: 2.7145x; 2.7145x over previous
#include <cuda_runtime.h>
#include <math.h>

#define BB 8
#define TT 256
#define KK 20
#define HH 768
#define VV 30522
#define TM1 255           // T-1
#define MR (TM1*BB)       // 2040 rows (t-major: r = t*BB + b)
#define G4 (4*HH)         // 3072
#define NBLK ((VV + 127)/128)   // 239 column blocks of logits
#define LJB 6             // LSTM j-slabs (512 gate-cols each)
#define LKS 8             // LSTM k-slices (96 each)
#define NEG_INF (-1e30f)

// ---------------- scratch (static device memory; no runtime allocs) ---------
static __device__ float g_trans[KK*KK];
static __device__ float g_emis[BB*TT*KK];          // [b][t][k]
static __device__ float g_alphas[TT*BB*KK];        // [t][b][k]
static __device__ float g_relaxed[TT*BB*KK];       // [t][b][k]
static __device__ int   g_z[TT*BB];                // [t][b]
static __device__ float g_enttok[BB*TT];           // [b][t]
static __device__ float g_dec[(size_t)MR*HH];      // [r][h]
static __device__ float g_wih_r[(size_t)G4*HH];    // [j'][k], j' = m*4+g
static __device__ float g_whh_r[(size_t)HH*G4];    // [k][m*4+g]
static __device__ float g_b4[G4];                  // [m*4+g]
static __device__ float g_xw[(size_t)MR*G4];       // [r][m*4+g], bias included
static __device__ float g_h[(size_t)MR*HH];        // [r][h]
static __device__ float g_c[BB*HH];
static __device__ float g_part[LJB*LKS*BB*512];    // LSTM split-K partials
static __device__ int   g_ctr[TM1*LJB];            // per-(t,jb) arrival counters
static __device__ float g_pmax[(size_t)MR*NBLK];   // per-row per-colblock max
static __device__ float g_psum[(size_t)MR*NBLK];   // per-row per-colblock sumexp
static __device__ float g_lse[MR];
static __device__ float g_tgtl[MR];

__device__ __forceinline__ float sigmoidf(float x){ return 1.f/(1.f+__expf(-x)); }

__device__ __forceinline__ unsigned f2tf(float x){
    unsigned r; asm("cvt.rna.tf32.f32 %0, %1;" : "=r"(r) : "f"(x)); return r;
}
__device__ __forceinline__ void mma_tf32(float c[4],
    unsigned a0, unsigned a1, unsigned a2, unsigned a3, unsigned b0, unsigned b1)
{
    asm volatile(
      "mma.sync.aligned.m16n8k8.row.col.f32.tf32.tf32.f32 "
      "{%0,%1,%2,%3}, {%4,%5,%6,%7}, {%8,%9}, {%0,%1,%2,%3};"
      : "+f"(c[0]), "+f"(c[1]), "+f"(c[2]), "+f"(c[3])
      : "r"(a0), "r"(a1), "r"(a2), "r"(a3), "r"(b0), "r"(b1));
}

// ---------------- transition = S @ S^T --------------------------------------
__global__ void k_trans(const float* __restrict__ S)
{
    int i = blockIdx.x, j = blockIdx.y;
    float s = 0.f;
    for (int k = threadIdx.x; k < HH; k += 128) s += S[i*HH+k]*S[j*HH+k];
    __shared__ float red[128];
    red[threadIdx.x] = s; __syncthreads();
    for (int o = 64; o > 0; o >>= 1) {
        if (threadIdx.x < o) red[threadIdx.x] += red[threadIdx.x+o];
        __syncthreads();
    }
    if (threadIdx.x == 0) g_trans[i*KK+j] = red[0];
}

// ---------------- counter reset ---------------------------------------------
__global__ void k_zero()
{
    int i = blockIdx.x*256 + threadIdx.x;
    if (i < TM1*LJB) g_ctr[i] = 0;
}

// ---------------- emission[b][t][k] = x_emb[b][t] . S[k] --------------------
__global__ void k_emis(const float* __restrict__ xemb, const float* __restrict__ S)
{
    int bt = blockIdx.x;                         // b*TT + t
    const float* xr = xemb + (size_t)bt*HH;
    int w = threadIdx.x >> 5, lane = threadIdx.x & 31;
    for (int k = w; k < KK; k += 8) {
        const float* sr = S + (size_t)k*HH;
        float s = 0.f;
        for (int i = lane; i < HH; i += 32) s += xr[i]*sr[i];
        for (int o = 16; o > 0; o >>= 1) s += __shfl_down_sync(0xffffffffu, s, o);
        if (lane == 0) g_emis[(size_t)bt*KK + k] = s;
    }
}

// ---------------- per-token entropy of softmax(emission) --------------------
__global__ void k_ent()
{
    int bt = blockIdx.x*256 + threadIdx.x;       // < BB*TT
    const float* e = g_emis + (size_t)bt*KK;
    float m = NEG_INF;
    for (int k = 0; k < KK; k++) m = fmaxf(m, e[k]);
    float se = 0.f;
    for (int k = 0; k < KK; k++) se += expf(e[k]-m);
    float lse = m + logf(se);
    float ent = 0.f;
    for (int k = 0; k < KK; k++) { float lp = e[k]-lse; ent -= expf(lp)*lp; }
    g_enttok[bt] = ent;
}

// ---------------- CRF forward recursion (sequential in t) -------------------
__global__ void k_fwd()
{
    __shared__ float sa[BB*KK];
    __shared__ float tr[KK*KK];
    int tid = threadIdx.x;
    for (int i = tid; i < KK*KK; i += blockDim.x) tr[i] = g_trans[i];
    if (tid < BB*KK) {
        int b = tid / KK, j = tid % KK;
        float a0 = g_emis[((size_t)b*TT + 0)*KK + j];
        sa[tid] = a0;
        g_alphas[tid] = a0;                      // t=0 slot
    }
    __syncthreads();
    for (int t = 1; t < TT; t++) {
        float a = 0.f;
        if (tid < BB*KK) {
            int b = tid / KK, j = tid % KK;
            float m = NEG_INF;
            #pragma unroll
            for (int k = 0; k < KK; k++) m = fmaxf(m, sa[b*KK+k] + tr[k*KK+j]);
            float se = 0.f;
            #pragma unroll
            for (int k = 0; k < KK; k++) se += expf(sa[b*KK+k] + tr[k*KK+j] - m);
            a = m + logf(se) + g_emis[((size_t)b*TT + t)*KK + j];
        }
        __syncthreads();
        if (tid < BB*KK) { sa[tid] = a; g_alphas[(size_t)t*BB*KK + tid] = a; }
        __syncthreads();
    }
}

// ---------------- relaxed backward sampling (warp b, lane k) ----------------
// argmax & softmax of (log_softmax(logits)+g) are shift-invariant -> skip lse.
__global__ void k_bwd(const float* __restrict__ gum)   // gum [t][b][k]
{
    int b = threadIdx.x >> 5, lane = threadIdx.x & 31;
    __shared__ float tr[KK*KK];
    for (int i = threadIdx.x; i < KK*KK; i += blockDim.x) tr[i] = g_trans[i];
    __syncthreads();
    int zn = 0;
    for (int t = TT-1; t >= 0; t--) {
        float y = NEG_INF;
        if (lane < KK) {
            float al = g_alphas[((size_t)t*BB + b)*KK + lane];
            float tv = (t == TT-1) ? 0.f : tr[lane*KK + zn];
            y = al + tv + gum[((size_t)t*BB + b)*KK + lane];
        }
        // argmax with lowest-index tiebreak (matches jnp.argmax)
        float bv = y; int bi = lane;
        for (int o = 16; o > 0; o >>= 1) {
            float ov = __shfl_down_sync(0xffffffffu, bv, o);
            int   oi = __shfl_down_sync(0xffffffffu, bi, o);
            if (ov > bv || (ov == bv && oi < bi)) { bv = ov; bi = oi; }
        }
        bv = __shfl_sync(0xffffffffu, bv, 0);
        bi = __shfl_sync(0xffffffffu, bi, 0);
        float e = (lane < KK) ? expf(y - bv) : 0.f;   // TAU = 1
        float se = e;
        for (int o = 16; o > 0; o >>= 1) se += __shfl_down_sync(0xffffffffu, se, o);
        se = __shfl_sync(0xffffffffu, se, 0);
        if (lane < KK) g_relaxed[((size_t)t*BB + b)*KK + lane] = e / se;
        if (lane == 0) g_z[t*BB + b] = bi;
        zn = bi;
    }
}

// ---------------- dec_in[r][h] = relaxed[t,b,:] @ S + emb[x[b][t]] ----------
__global__ void k_dec(const float* __restrict__ S, const float* __restrict__ emb,
                      const int* __restrict__ x)
{
    int r = blockIdx.x;                           // r = t*BB + b, t < TM1
    int t = r / BB, b = r % BB;
    __shared__ float rl[KK];
    if (threadIdx.x < KK) rl[threadIdx.x] = g_relaxed[((size_t)t*BB + b)*KK + threadIdx.x];
    __syncthreads();
    const float* er = emb + (size_t)x[b*TT + t]*HH;
    for (int h = threadIdx.x; h < HH; h += 256) {
        float s = er[h];
        #pragma unroll
        for (int k = 0; k < KK; k++) s += rl[k]*S[(size_t)k*HH + h];
        g_dec[(size_t)r*HH + h] = s;
    }
}

// ---------------- weight repacking (gate-interleaved) -----------------------
__global__ void k_packwih(const float* __restrict__ W)
{
    size_t i = (size_t)blockIdx.x*256 + threadIdx.x;
    if (i >= (size_t)G4*HH) return;
    int jp = (int)(i / HH), k = (int)(i % HH);
    int g = jp & 3, m = jp >> 2;
    g_wih_r[i] = W[(size_t)(g*HH + m)*HH + k];
}
__global__ void k_packwhh(const float* __restrict__ W)
{
    size_t i = (size_t)blockIdx.x*256 + threadIdx.x;
    if (i >= (size_t)HH*G4) return;
    int k = (int)(i / G4), j = (int)(i % G4);
    int m = j >> 2, g = j & 3;
    g_whh_r[i] = W[(size_t)(g*HH + m)*HH + k];
}
__global__ void k_packb(const float* __restrict__ bl)
{
    int j = blockIdx.x*256 + threadIdx.x;
    if (j < G4) g_b4[j] = bl[(j & 3)*HH + (j >> 2)];
}

// ---------------- fp32 NT GEMM: C[M,N] = A[M,768] * Bm[N,768]^T + bias ------
__global__ void __launch_bounds__(256)
k_sgemm(const float* __restrict__ A, const float* __restrict__ Bm,
        const float* __restrict__ bias, float* __restrict__ C, int M, int N)
{
    const int K = HH;
    __shared__ __align__(16) float As[16][64];
    __shared__ __align__(16) float Bs[16][64];
    int bn0 = blockIdx.x*64, bm0 = blockIdx.y*64;
    int tid = threadIdx.x;
    int tx = tid & 15, ty = tid >> 4;
    int lr = tid >> 2, lk = (tid & 3)*4;
    float acc[16];
    #pragma unroll
    for (int i = 0; i < 16; i++) acc[i] = 0.f;
    const float* Ap = A + (size_t)(bm0+lr)*K + lk;
    const float* Bp = Bm + (size_t)(bn0+lr)*K + lk;
    bool aval = (bm0+lr) < M;
    bool bval = (bn0+lr) < N;
    for (int k0 = 0; k0 < K; k0 += 16) {
        float4 av = aval ? *(const float4*)(Ap + k0) : make_float4(0,0,0,0);
        float4 bv = bval ? *(const float4*)(Bp + k0) : make_float4(0,0,0,0);
        As[lk+0][lr]=av.x; As[lk+1][lr]=av.y; As[lk+2][lr]=av.z; As[lk+3][lr]=av.w;
        Bs[lk+0][lr]=bv.x; Bs[lk+1][lr]=bv.y; Bs[lk+2][lr]=bv.z; Bs[lk+3][lr]=bv.w;
        __syncthreads();
        #pragma unroll
        for (int kk = 0; kk < 16; kk++) {
            float4 a = *(const float4*)&As[kk][ty*4];
            float4 b = *(const float4*)&Bs[kk][tx*4];
            acc[0]  += a.x*b.x; acc[1]  += a.x*b.y; acc[2]  += a.x*b.z; acc[3]  += a.x*b.w;
            acc[4]  += a.y*b.x; acc[5]  += a.y*b.y; acc[6]  += a.y*b.z; acc[7]  += a.y*b.w;
            acc[8]  += a.z*b.x; acc[9]  += a.z*b.y; acc[10] += a.z*b.z; acc[11] += a.z*b.w;
            acc[12] += a.w*b.x; acc[13] += a.w*b.y; acc[14] += a.w*b.z; acc[15] += a.w*b.w;
        }
        __syncthreads();
    }
    #pragma unroll
    for (int i = 0; i < 4; i++) {
        int r = bm0 + ty*4 + i;
        if (r >= M) continue;
        #pragma unroll
        for (int j = 0; j < 4; j++) {
            int c = bn0 + tx*4 + j;
            if (c < N) C[(size_t)r*N + c] = acc[i*4+j] + (bias ? bias[c] : 0.f);
        }
    }
}

// ---------------- LSTM t=0 (h=c=0): pointwise on xw only --------------------
__global__ void k_step0()
{
    int m = blockIdx.x*128 + threadIdx.x;         // hidden unit
    #pragma unroll
    for (int b = 0; b < BB; b++) {
        float4 g4 = *(const float4*)(g_xw + (size_t)b*G4 + m*4);
        float ig = sigmoidf(g4.x);
        float gg = tanhf(g4.z),    og = sigmoidf(g4.w);
        float c = ig*gg;
        float h = og*tanhf(c);
        g_c[b*HH + m] = c;
        g_h[(size_t)b*HH + m] = h;
    }
}

// ---------------- LSTM step t>0: split-K matvec + last-block combine --------
__global__ void __launch_bounds__(128)
k_step(int t)
{
    __shared__ float hsm[BB][96];
    __shared__ int s_last;
    int jb = blockIdx.x;                          // 0..5  (512 gate-cols)
    int ks = blockIdx.y;                          // 0..7  (96 k each)
    int tid = threadIdx.x;                        // 128

    // load h_prev slice [8][96] into smem
    for (int i = tid; i < BB*96; i += 128) {
        int b = i / 96, kk = i % 96;
        hsm[b][kk] = g_h[((size_t)(t-1)*BB + b)*HH + ks*96 + kk];
    }
    __syncthreads();

    int jv = jb*128 + tid;                        // global float4 gate-col
    const float4* Wp = ((const float4*)g_whh_r) + jv;   // row stride HH float4s
    float4 acc[BB];
    #pragma unroll
    for (int b = 0; b < BB; b++) acc[b] = make_float4(0,0,0,0);

    int kbase = ks*96;
    #pragma unroll 4
    for (int kq = 0; kq < 24; kq++) {
        int k = kbase + kq*4;
        float4 w0 = Wp[(size_t)(k+0)*HH];
        float4 w1 = Wp[(size_t)(k+1)*HH];
        float4 w2 = Wp[(size_t)(k+2)*HH];
        float4 w3 = Wp[(size_t)(k+3)*HH];
        #pragma unroll
        for (int b = 0; b < BB; b++) {
            float4 h4 = *(const float4*)&hsm[b][kq*4];
            acc[b].x += h4.x*w0.x + h4.y*w1.x + h4.z*w2.x + h4.w*w3.x;
            acc[b].y += h4.x*w0.y + h4.y*w1.y + h4.z*w2.y + h4.w*w3.y;
            acc[b].z += h4.x*w0.z + h4.y*w1.z + h4.z*w2.z + h4.w*w3.z;
            acc[b].w += h4.x*w0.w + h4.y*w1.w + h4.z*w2.w + h4.w*w3.w;
        }
    }
    #pragma unroll
    for (int b = 0; b < BB; b++)
        *(float4*)&g_part[(((size_t)jb*LKS + ks)*BB + b)*512 + tid*4] = acc[b];

    __threadfence();
    if (tid == 0) {
        int old = atomicAdd(&g_ctr[t*LJB + jb], 1);
        s_last = (old == LKS-1);
    }
    __syncthreads();
    if (!s_last) return;

    // last-arriving block for this j-slab: combine + pointwise
    int m = jb*128 + tid;                         // hidden unit
    #pragma unroll
    for (int b = 0; b < BB; b++) {
        float4 g4 = *(const float4*)(g_xw + ((size_t)t*BB + b)*G4 + m*4);
        #pragma unroll
        for (int k2 = 0; k2 < LKS; k2++) {
            float4 p = *(const float4*)&g_part[(((size_t)jb*LKS + k2)*BB + b)*512 + tid*4];
            g4.x += p.x; g4.y += p.y; g4.z += p.z; g4.w += p.w;
        }
        float c_old = g_c[b*HH + m];
        float ig = sigmoidf(g4.x), fg = sigmoidf(g4.y);
        float gg = tanhf(g4.z),    og = sigmoidf(g4.w);
        float c  = fg*c_old + ig*gg;
        float h  = og*tanhf(c);
        g_c[b*HH + m] = c;
        g_h[((size_t)t*BB + b)*HH + m] = h;
    }
}

// ---------------- tf32 MMA logits GEMM + fused per-colblock softmax stats ---
// A = g_h [MR][768], B = W_out [VV][768], per (row, nb): max & sumexp of
// (A@B^T + bias) over the 128-col slab nb. Logits never hit memory.
__global__ void __launch_bounds__(256)
k_mma_logits(const float* __restrict__ A, const float* __restrict__ Bw,
             const float* __restrict__ bias)
{
    __shared__ unsigned As[16][132];
    __shared__ unsigned Bs[16][132];
    __shared__ float stm[2][128], sts[2][128];
    int mb = blockIdx.x, nb = blockIdx.y;
    int bm0 = mb*128, bn0 = nb*128;
    int tid = threadIdx.x, lane = tid & 31, wid = tid >> 5;
    int wm = wid & 3, wn = wid >> 2;

    int lrow = tid >> 1, lk = (tid & 1)*8;
    const float* Aptr = A  + (size_t)(bm0+lrow)*HH + lk;
    const float* Bptr = Bw + (size_t)(bn0+lrow)*HH + lk;
    bool av = (bm0 + lrow) < MR;
    bool bv = (bn0 + lrow) < VV;

    float acc[2][8][4];
    #pragma unroll
    for (int i = 0; i < 2; i++)
        #pragma unroll
        for (int j = 0; j < 8; j++)
            #pragma unroll
            for (int q = 0; q < 4; q++) acc[i][j][q] = 0.f;

    float4 ra0 = av ? *(const float4*)(Aptr)     : make_float4(0,0,0,0);
    float4 ra1 = av ? *(const float4*)(Aptr + 4) : make_float4(0,0,0,0);
    float4 rb0 = bv ? *(const float4*)(Bptr)     : make_float4(0,0,0,0);
    float4 rb1 = bv ? *(const float4*)(Bptr + 4) : make_float4(0,0,0,0);

    for (int kt = 0; kt < HH/16; kt++) {
        __syncthreads();
        As[lk+0][lrow]=f2tf(ra0.x); As[lk+1][lrow]=f2tf(ra0.y);
        As[lk+2][lrow]=f2tf(ra0.z); As[lk+3][lrow]=f2tf(ra0.w);
        As[lk+4][lrow]=f2tf(ra1.x); As[lk+5][lrow]=f2tf(ra1.y);
        As[lk+6][lrow]=f2tf(ra1.z); As[lk+7][lrow]=f2tf(ra1.w);
        Bs[lk+0][lrow]=f2tf(rb0.x); Bs[lk+1][lrow]=f2tf(rb0.y);
        Bs[lk+2][lrow]=f2tf(rb0.z); Bs[lk+3][lrow]=f2tf(rb0.w);
        Bs[lk+4][lrow]=f2tf(rb1.x); Bs[lk+5][lrow]=f2tf(rb1.y);
        Bs[lk+6][lrow]=f2tf(rb1.z); Bs[lk+7][lrow]=f2tf(rb1.w);
        __syncthreads();
        if (kt+1 < HH/16) {
            int off = (kt+1)*16;
            ra0 = av ? *(const float4*)(Aptr + off)     : make_float4(0,0,0,0);
            ra1 = av ? *(const float4*)(Aptr + off + 4) : make_float4(0,0,0,0);
            rb0 = bv ? *(const float4*)(Bptr + off)     : make_float4(0,0,0,0);
            rb1 = bv ? *(const float4*)(Bptr + off + 4) : make_float4(0,0,0,0);
        }
        #pragma unroll
        for (int k8 = 0; k8 < 16; k8 += 8) {
            unsigned af[2][4];
            #pragma unroll
            for (int mf = 0; mf < 2; mf++) {
                int m0 = wm*32 + mf*16 + (lane >> 2);
                int kr = k8 + (lane & 3);
                af[mf][0] = As[kr][m0];
                af[mf][1] = As[kr][m0+8];
                af[mf][2] = As[kr+4][m0];
                af[mf][3] = As[kr+4][m0+8];
            }
            #pragma unroll
            for (int nf = 0; nf < 8; nf++) {
                int n0 = wn*64 + nf*8 + (lane >> 2);
                int kr = k8 + (lane & 3);
                unsigned b0 = Bs[kr][n0];
                unsigned b1 = Bs[kr+4][n0];
                mma_tf32(acc[0][nf], af[0][0], af[0][1], af[0][2], af[0][3], b0, b1);
                mma_tf32(acc[1][nf], af[1][0], af[1][1], af[1][2], af[1][3], b0, b1);
            }
        }
    }

    // epilogue: bias + per-row slab (max, sumexp)
    float bc[8][2];
    #pragma unroll
    for (int nf = 0; nf < 8; nf++) {
        #pragma unroll
        for (int jj = 0; jj < 2; jj++) {
            int c = bn0 + wn*64 + nf*8 + (lane & 3)*2 + jj;
            bc[nf][jj] = (c < VV) ? bias[c] : NEG_INF;
        }
    }
    #pragma unroll
    for (int mf = 0; mf < 2; mf++) {
        #pragma unroll
        for (int half = 0; half < 2; half++) {
            float v[8][2], m = NEG_INF;
            #pragma unroll
            for (int nf = 0; nf < 8; nf++)
                #pragma unroll
                for (int jj = 0; jj < 2; jj++) {
                    float b = bc[nf][jj];
                    float val = (b > -1e29f) ? acc[mf][nf][half*2+jj] + b : NEG_INF;
                    v[nf][jj] = val;
                    m = fmaxf(m, val);
                }
            m = fmaxf(m, __shfl_xor_sync(0xffffffffu, m, 1));
            m = fmaxf(m, __shfl_xor_sync(0xffffffffu, m, 2));
            float s = 0.f;
            #pragma unroll
            for (int nf = 0; nf < 8; nf++)
                #pragma unroll
                for (int jj = 0; jj < 2; jj++)
                    if (v[nf][jj] > -1e29f) s += __expf(v[nf][jj] - m);
            s += __shfl_xor_sync(0xffffffffu, s, 1);
            s += __shfl_xor_sync(0xffffffffu, s, 2);
            if ((lane & 3) == 0) {
                int rloc = wm*32 + mf*16 + (lane >> 2) + half*8;
                stm[wn][rloc] = m;
                sts[wn][rloc] = s;
            }
        }
    }
    __syncthreads();
    if (tid < 128) {
        float m0 = stm[0][tid], m1 = stm[1][tid];
        float s0 = sts[0][tid], s1 = sts[1][tid];
        float mm = fmaxf(m0, m1);
        float ss = s0*__expf(m0 - mm) + s1*__expf(m1 - mm);
        int r = bm0 + tid;
        if (r < MR) {
            g_pmax[(size_t)r*NBLK + nb] = mm;
            g_psum[(size_t)r*NBLK + nb] = ss;
        }
    }
}

// ---------------- reduce partial stats -> lse per row -----------------------
__global__ void k_red()
{
    int r = blockIdx.x*8 + (threadIdx.x >> 5);
    int lane = threadIdx.x & 31;
    if (r >= MR) return;
    const float* pm = g_pmax + (size_t)r*NBLK;
    const float* ps = g_psum + (size_t)r*NBLK;
    float m = NEG_INF;
    for (int i = lane; i < NBLK; i += 32) m = fmaxf(m, pm[i]);
    for (int o = 16; o > 0; o >>= 1) m = fmaxf(m, __shfl_xor_sync(0xffffffffu, m, o));
    float s = 0.f;
    for (int i = lane; i < NBLK; i += 32) s += ps[i]*__expf(pm[i] - m);
    for (int o = 16; o > 0; o >>= 1) s += __shfl_xor_sync(0xffffffffu, s, o);
    if (lane == 0) g_lse[r] = m + __logf(s);
}

// ---------------- target logit (fp32 dot) -----------------------------------
__global__ void k_tgt(const float* __restrict__ Wout, const float* __restrict__ bout,
                      const int* __restrict__ x)
{
    int r = blockIdx.x*8 + (threadIdx.x >> 5);
    int lane = threadIdx.x & 31;
    if (r >= MR) return;
    int t = r >> 3, b = r & 7;
    int tgt = x[b*TT + t + 1];
    const float* hr = g_h + (size_t)r*HH;
    const float* wr = Wout + (size_t)tgt*HH;
    float s = 0.f;
    for (int i = lane; i < HH; i += 32) s += hr[i]*wr[i];
    for (int o = 16; o > 0; o >>= 1) s += __shfl_xor_sync(0xffffffffu, s, o);
    if (lane == 0) g_tgtl[r] = s + bout[tgt];
}

// ---------------- final loss + output ---------------------------------------
__global__ void k_final(const int* __restrict__ am, float* __restrict__ out, int out_size)
{
    int tid = threadIdx.x;
    float s_ent = 0.f, s_m = 0.f, s_lp = 0.f, s_tm = 0.f;
    for (int i = tid; i < BB*TT; i += 256) {
        float mk = (float)am[i];
        s_ent += g_enttok[i]*mk;
        s_m   += mk;
    }
    for (int r = tid; r < MR; r += 256) {
        int t = r / BB, b = r % BB;
        float mk = (float)am[b*TT + t + 1];
        s_lp += (g_tgtl[r] - g_lse[r])*mk;
        s_tm += mk;
    }
    __shared__ float r0[256], r1[256], r2[256], r3[256];
    r0[tid]=s_ent; r1[tid]=s_m; r2[tid]=s_lp; r3[tid]=s_tm;
    __syncthreads();
    for (int o = 128; o > 0; o >>= 1) {
        if (tid < o) { r0[tid]+=r0[tid+o]; r1[tid]+=r1[tid+o];
                       r2[tid]+=r2[tid+o]; r3[tid]+=r3[tid+o]; }
        __syncthreads();
    }
    if (tid == 0) {
        float loss = -((r2[0]/r3[0]) + 1.0f*(r0[0]/r1[0]));   // Z_BETA = 1
        if (out_size != BB*TT) out[0] = loss;
    }
    __syncthreads();
    int off = (out_size == BB*TT) ? 0 : 1;
    if (out_size >= BB*TT + off) {
        for (int i = tid; i < BB*TT; i += 256) {
            int b = i / TT, t = i % TT;
            out[off + i] = (float)g_z[t*BB + b];              // z_sample[b][t]
        }
    }
}

// ---------------- host ------------------------------------------------------
extern "C" void kernel_launch(void* const* d_in, const int* in_sizes, int n_in,
                              void* d_out, int out_size)
{
    (void)in_sizes; (void)n_in;
    const float* x_emb = (const float*)d_in[0];
    const float* S     = (const float*)d_in[1];
    const float* emb   = (const float*)d_in[2];
    const float* Wih   = (const float*)d_in[3];
    const float* Whh   = (const float*)d_in[4];
    const float* bl    = (const float*)d_in[5];
    const float* Wout  = (const float*)d_in[6];
    const float* bout  = (const float*)d_in[7];
    const float* gum   = (const float*)d_in[8];
    const int*   x     = (const int*)d_in[9];
    const int*   am    = (const int*)d_in[10];

    float *p_dec, *p_wihr, *p_b4, *p_xw, *p_h;
    cudaGetSymbolAddress((void**)&p_dec,  g_dec);
    cudaGetSymbolAddress((void**)&p_wihr, g_wih_r);
    cudaGetSymbolAddress((void**)&p_b4,   g_b4);
    cudaGetSymbolAddress((void**)&p_xw,   g_xw);
    cudaGetSymbolAddress((void**)&p_h,    g_h);

    k_zero<<<(TM1*LJB + 255)/256, 256>>>();
    dim3 gt(KK, KK);
    k_trans<<<gt, 128>>>(S);
    k_emis<<<BB*TT, 256>>>(x_emb, S);
    k_ent<<<(BB*TT)/256, 256>>>();
    k_fwd<<<1, 256>>>();
    k_bwd<<<1, BB*32>>>(gum);
    k_dec<<<MR, 256>>>(S, emb, x);
    k_packwih<<<(int)(((size_t)G4*HH + 255)/256), 256>>>(Wih);
    k_packwhh<<<(int)(((size_t)HH*G4 + 255)/256), 256>>>(Whh);
    k_packb<<<(G4 + 255)/256, 256>>>(bl);

    // xW = dec_in @ W_ih^T (gate-interleaved) + b  (fp32 for recurrence safety)
    k_sgemm<<<dim3(G4/64, (MR + 63)/64), 256>>>(p_dec, p_wihr, p_b4, p_xw, MR, G4);

    // sequential LSTM
    k_step0<<<LJB, 128>>>();
    for (int t = 1; t < TM1; t++)
        k_step<<<dim3(LJB, LKS), 128>>>(t);

    // logits GEMM (tf32 tensor cores) fused with softmax partial stats
    k_mma_logits<<<dim3((MR + 127)/128, NBLK), 256>>>(p_h, Wout, bout);
    k_red<<<MR/8, 256>>>();
    k_tgt<<<MR/8, 256>>>(Wout, bout, x);
    k_final<<<1, 256>>>(am, (float*)d_out, out_size);
}